// round 17
// baseline (speedup 1.0000x reference)
#include <cuda_runtime.h>

// PBKDF2-toy, serial single-warp register kernel. R17: remainder-peel test
// on the certified best (R8/R16, 184.4-185.0us, issue ~86%). The unroll-4
// loop ran 999 iters (999 = 4*249 + 3); remainder handling is opaque and
// was pathological at unroll 8 (R15). Here the main loop is exactly 996 =
// 4*249 (constant bounds, zero remainder) and the 3 leftover iterations
// are peeled as straight-line code. Everything else byte-identical to best.
// Floor audit (final): mix 2-op/step minimal, absorb 16-op minimal, F-fold
// 32-slot minimal; 304 slots/iter is the formulation floor (~164us).
// Harness dtype shims: float32 out, dtype-sniffed in (proven R3).

__device__ __forceinline__ unsigned load_byte(const void* p, int i) {
    int v = ((const int*)p)[i];
    if ((unsigned)v <= 255u) return (unsigned)v;   // int32 input
    return (unsigned)(int)__int_as_float(v);       // float32 input
}

// hi*65536 + lo as a single IMAD (fma pipe); benign to scheduling (R8).
__device__ __forceinline__ unsigned pack16(unsigned hi, unsigned lo) {
    unsigned t;
    asm("mad.lo.u32 %0, %1, 65536, %2;" : "=r"(t) : "r"(hi), "r"(lo));
    return t;
}

// One full PBKDF2 iteration: absorb(collapsed) + 4 mix rounds, with the
// packed F-fold fused into round-4 steps 16..31. Inlined everywhere.
__device__ __forceinline__ void iter_body(unsigned r[32], const unsigned c[16],
                                          unsigned Fp[16]) {
    #pragma unroll
    for (int j = 0; j < 16; j++) {
        unsigned t = r[j];
        r[j] = c[j] + r[16 + j];          // 9-bit OK: mix LOP3 re-masks
        r[16 + j] = t;                    // order-2 swap -> pure renaming
    }
    #pragma unroll
    for (int rd = 0; rd < 3; rd++) {
        #pragma unroll
        for (int i = 0; i < 32; i++)
            r[i] = (r[i] ^ (r[(i + 17) & 31] + r[(i + 11) & 31])) & 255u;
    }
    #pragma unroll
    for (int i = 0; i < 16; i++)
        r[i] = (r[i] ^ (r[(i + 17) & 31] + r[(i + 11) & 31])) & 255u;
    #pragma unroll
    for (int i = 16; i < 32; i++) {
        r[i] = (r[i] ^ (r[(i + 17) & 31] + r[(i + 11) & 31])) & 255u;
        Fp[i - 16] ^= pack16(r[i], r[i - 16]);   // IMAD (fma) + LOP3 (alu)
    }
}

__global__ void __launch_bounds__(32, 1)
Model_62955630625117_kernel(const void* __restrict__ pw_in,
                            const void* __restrict__ salt_in,
                            float* __restrict__ out) {
    // All lanes uniform & convergent; lane 0 writes at the end.
    unsigned c[16];    // (pw[j]*31) & 255, loop-invariant
    unsigned r[32];    // hash state U (mix LOP3 keeps bytes 8-bit)
    unsigned Fp[16];   // packed xor accumulator: lo16 = F[i], hi16 = F[i+16]

    #pragma unroll
    for (int j = 0; j < 16; j++) {
        unsigned p = load_byte(pw_in, j);
        c[j] = (p * 31u) & 255u;
        r[j] = p;
    }
    #pragma unroll
    for (int j = 0; j < 16; j++) r[16 + j] = load_byte(salt_in, j);

    // First hmac message = salt(16) ++ block_num{0,0,0,1}
    r[0] = c[0];
    r[1] = c[1];
    r[2] = c[2];
    r[3] = (c[3] + 1u) & 255u;

    // U0 mix
    #pragma unroll
    for (int rd = 0; rd < 4; rd++) {
        #pragma unroll
        for (int i = 0; i < 32; i++)
            r[i] = (r[i] ^ (r[(i + 17) & 31] + r[(i + 11) & 31])) & 255u;
    }
    #pragma unroll
    for (int i = 0; i < 16; i++)
        Fp[i] = pack16(r[i + 16], r[i]);           // F init = U0 (packed)

    // 999 iterations = 996 (exact 4x249 unrolled loop) + 3 peeled.
    #pragma unroll 4
    for (int it = 0; it < 996; it++)
        iter_body(r, c, Fp);
    iter_body(r, c, Fp);
    iter_body(r, c, Fp);
    iter_body(r, c, Fp);

    if (threadIdx.x == 0) {
        #pragma unroll
        for (int i = 0; i < 16; i++) {
            out[i]      = (float)(Fp[i] & 0xFFFFu);
            out[i + 16] = (float)(Fp[i] >> 16);
        }
    }
}

extern "C" void kernel_launch(void* const* d_in, const int* in_sizes, int n_in,
                              void* d_out, int out_size) {
    const void* password = d_in[0];
    const void* salt     = (n_in >= 2) ? d_in[1] : (const void*)((const int*)d_in[0] + 16);
    float* out           = (float*)d_out;
    Model_62955630625117_kernel<<<1, 32>>>(password, salt, out);
}